// round 8
// baseline (speedup 1.0000x reference)
#include <cuda_runtime.h>
#include <math.h>

// Problem constants
#define S   2048
#define B   4
#define D   1024
#define M_ROWS (S*B)   // 8192 rows, time-major: row = t*B + b

typedef unsigned long long ull;

// ---------------------------------------------------------------------------
// Scratch buffers (device globals; no allocation allowed)
// ---------------------------------------------------------------------------
__device__ float g_ret   [(size_t)M_ROWS*D];
__device__ float g_inp   [(size_t)M_ROWS*D];
__device__ float g_gpre  [(size_t)M_ROWS*D];
__device__ float g_c     [(size_t)M_ROWS*D];   // c; later d = u@A^T + c
__device__ float g_gate  [(size_t)M_ROWS*D];
__device__ float g_u     [(size_t)M_ROWS*D];
__device__ float g_states[(size_t)M_ROWS*D];
__device__ float        g_xbuf[2][B][D];       // blended exchange, 2-deep
__device__ unsigned int g_flags[4][32];        // per-group per-producer epoch

__global__ void init_misc_kernel() {
    int i = blockIdx.x*blockDim.x + threadIdx.x;
    if (i < 4*32) ((unsigned int*)g_flags)[i] = 0u;
    if (i < B*D)  ((float*)g_xbuf)[i] = 0.f;   // buf0 = zeros (epoch 0)
}

// ---------------------------------------------------------------------------
// f32x2 + memory-order helpers
// ---------------------------------------------------------------------------
__device__ __forceinline__ ull pack2(float x, float y) {
    ull r; asm("mov.b64 %0, {%1, %2};" : "=l"(r) : "f"(x), "f"(y)); return r;
}
__device__ __forceinline__ void fma2(ull& d, ull a, ull b) {
    asm("fma.rn.f32x2 %0, %1, %2, %0;" : "+l"(d) : "l"(a), "l"(b));
}
__device__ __forceinline__ float2 unpack2(ull a) {
    float2 r; asm("mov.b64 {%0, %1}, %2;" : "=f"(r.x), "=f"(r.y) : "l"(a)); return r;
}
__device__ __forceinline__ ull ld_acq64(const ull* p) {
    ull v;
    asm volatile("ld.acquire.gpu.u64 %0, [%1];" : "=l"(v) : "l"(p) : "memory");
    return v;
}
__device__ __forceinline__ void st_rel32(unsigned int* p, unsigned int v) {
    asm volatile("st.release.gpu.u32 [%0], %1;" :: "l"(p), "r"(v) : "memory");
}
__device__ __forceinline__ float4 ld_cg_f4(const float4* p) {
    float4 v;
    asm volatile("ld.global.cg.v4.f32 {%0,%1,%2,%3}, [%4];"
                 : "=f"(v.x), "=f"(v.y), "=f"(v.z), "=f"(v.w) : "l"(p) : "memory");
    return v;
}

// ---------------------------------------------------------------------------
// Phase 1: retention scan with decay halo (decay=0.9 -> 256-step halo exact
// to ~2e-12 relative).
// ---------------------------------------------------------------------------
__global__ void scan_kernel(const float* __restrict__ q,
                            const float* __restrict__ k,
                            const float* __restrict__ v,
                            const float* __restrict__ dec)
{
    int chunk = blockIdx.x;                 // 16 chunks of 128 steps
    int b     = blockIdx.y;
    int d     = blockIdx.z*256 + threadIdx.x;
    float decay = dec[d >> 6];
    int t0 = chunk*128;
    int start = t0 - 256; if (start < 0) start = 0;
    float r = 0.f;
    const float* kb = k + ((size_t)b*S)*D + d;
    const float* vb = v + ((size_t)b*S)*D + d;
    const float* qb = q + ((size_t)b*S)*D + d;
    for (int tt = start; tt < t0 + 128; ++tt) {
        size_t off = (size_t)tt*D;
        r = decay*r + kb[off]*vb[off];
        if (tt >= t0) g_ret[((size_t)tt*B + b)*D + d] = qb[off]*r;
    }
}

// ---------------------------------------------------------------------------
// fp32 SGEMM: C[m,n] = sum_k X[m,k]*W[n,k] (+bias) (+Cin). M=8192, N=K=1024.
// 128x128 tile, BK=8, 256 thr, 8x8/thread.
// A stored DUPLICATED in smem ({a,a} pairs) so the inner loop reads packed
// f32x2 operands directly. B fragment re-mapped to stride-32 pairs
// (n = tx*2 + j*32) -> LDS.64 at 8B lane stride, conflict-free.
// ---------------------------------------------------------------------------
#define APAD 264   // 8-row A-dup stride (floats): 264*4 % 16 == 0, breaks bank alias
#define BPAD 132   // B row stride (floats)

__global__ __launch_bounds__(256, 2)
void sgemm_kernel(const float* __restrict__ X, const float* __restrict__ W,
                  const float* __restrict__ bias, const float* Cin,
                  float* Cout, int permute)
{
    __shared__ float As[2][8][APAD];   // dup pairs: As[k][2m], As[k][2m+1]
    __shared__ float Bs[2][8][BPAD];

    int tid = threadIdx.x;
    int m0 = blockIdx.y*128, n0 = blockIdx.x*128;
    int lrow = tid >> 1;
    int lk4  = (tid & 1)*4;
    const float4* Xg = (const float4*)(X + (size_t)(m0+lrow)*D + lk4);
    const float4* Wg = (const float4*)(W + (size_t)(n0+lrow)*D + lk4);
    int ty = tid >> 4, tx = tid & 15;

    ull acc[8][4];   // 8 m-rows x 4 n-pairs (n = tx*2 + j*32)
    #pragma unroll
    for (int i = 0; i < 8; ++i)
        #pragma unroll
        for (int j = 0; j < 4; ++j) acc[i][j] = 0ull;

    // prologue: fill buffer 0
    {
        float4 ra = Xg[0], rb = Wg[0];
        float av[4] = {ra.x, ra.y, ra.z, ra.w};
        float bv[4] = {rb.x, rb.y, rb.z, rb.w};
        #pragma unroll
        for (int j = 0; j < 4; ++j) {
            *(ull*)&As[0][lk4+j][2*lrow] = pack2(av[j], av[j]);
            Bs[0][lk4+j][lrow] = bv[j];
        }
    }
    __syncthreads();

    int cur = 0;
    #pragma unroll 1
    for (int kt = 0; kt < 128; ++kt) {
        float4 ra2, rb2;
        if (kt < 127) { ra2 = Xg[(kt+1)*2]; rb2 = Wg[(kt+1)*2]; }

        #pragma unroll
        for (int kk = 0; kk < 8; ++kk) {
            const ulonglong2* ap = (const ulonglong2*)&As[cur][kk][ty*16];
            ulonglong2 a01 = ap[0], a23 = ap[1], a45 = ap[2], a67 = ap[3];
            ull ad[8] = {a01.x, a01.y, a23.x, a23.y, a45.x, a45.y, a67.x, a67.y};
            ull bp[4];
            bp[0] = *(const ull*)&Bs[cur][kk][tx*2];
            bp[1] = *(const ull*)&Bs[cur][kk][tx*2 + 32];
            bp[2] = *(const ull*)&Bs[cur][kk][tx*2 + 64];
            bp[3] = *(const ull*)&Bs[cur][kk][tx*2 + 96];
            #pragma unroll
            for (int i = 0; i < 8; ++i)
                #pragma unroll
                for (int j = 0; j < 4; ++j)
                    fma2(acc[i][j], bp[j], ad[i]);
        }

        if (kt < 127) {
            int nb = cur ^ 1;
            float av[4] = {ra2.x, ra2.y, ra2.z, ra2.w};
            float bv[4] = {rb2.x, rb2.y, rb2.z, rb2.w};
            #pragma unroll
            for (int j = 0; j < 4; ++j) {
                *(ull*)&As[nb][lk4+j][2*lrow] = pack2(av[j], av[j]);
                Bs[nb][lk4+j][lrow] = bv[j];
            }
            __syncthreads();
            cur = nb;
        }
    }

    #pragma unroll
    for (int i = 0; i < 8; ++i) {
        int m = m0 + ty*8 + i;
        size_t obase;
        if (!permute) obase = (size_t)m*D;
        else { int t = m >> 2; int bb = m & 3; obase = ((size_t)bb*S + t)*D; }
        #pragma unroll
        for (int j = 0; j < 4; ++j) {
            float2 v = unpack2(acc[i][j]);
            int n = n0 + tx*2 + j*32;
            float v0 = v.x, v1 = v.y;
            if (bias) { v0 += bias[n]; v1 += bias[n+1]; }
            if (Cin)  { v0 += Cin[(size_t)m*D + n]; v1 += Cin[(size_t)m*D + n+1]; }
            Cout[obase + n]   = v0;
            Cout[obase + n+1] = v1;
        }
    }
}

// ---------------------------------------------------------------------------
// gate = sigmoid(gpre); u = (1-gate)*inp
// ---------------------------------------------------------------------------
__global__ void gate_kernel()
{
    size_t i = (size_t)blockIdx.x*blockDim.x + threadIdx.x;
    if (i < (size_t)M_ROWS*D) {
        float gp = g_gpre[i];
        float gt = 1.f/(1.f + expf(-gp));
        g_gate[i] = gt;
        g_u[i]    = (1.f - gt)*g_inp[i];
    }
}

// ---------------------------------------------------------------------------
// Sequential phase: state_t = tanh((g_t (*) state_{t-1}) @ A^T + d_t)
// 4 independent batch groups x 32 CTAs x 512 threads. NO grid barrier:
// producers release per-chunk epoch flags; each reader warp polls ONE
// ld.acquire.u64 covering the 2 producer flags its 64-k slice depends on.
// 2-deep value buffer + monotonic flags (>= t) make max-skew-2 safe.
// ---------------------------------------------------------------------------
__global__ __launch_bounds__(512, 1)
void seq_kernel(const float* __restrict__ A)
{
    __shared__ float red[16*32];

    int tid = threadIdx.x;
    int w   = tid >> 5, l = tid & 31;
    int grp = blockIdx.x & 3;          // batch
    int cid = blockIdx.x >> 2;         // 0..31 within group
    int col = cid*32 + l;
    int k0  = w*64;

    // Register-resident A slice: A[col, k0 .. k0+63] as 32 f32x2 pairs
    ull A2[32];
    {
        const ulonglong2* ap = (const ulonglong2*)(A + (size_t)col*D + k0);
        #pragma unroll
        for (int i = 0; i < 16; ++i) {
            ulonglong2 u = ap[i];
            A2[2*i] = u.x; A2[2*i+1] = u.y;
        }
    }

    // this warp's k-slice depends on producers cid = 2w and 2w+1
    const ull* flagp = (const ull*)&g_flags[grp][w*2];

    // writer-lane prefetch: d row for step 0, gate row for step 1
    float dval = 0.f, gval = 0.f;
    if (tid < 32) {
        dval = __ldg(&g_c   [(size_t)grp*D + col]);
        gval = __ldg(&g_gate[((size_t)1*B + grp)*D + col]);
    }

    for (int t = 0; t < S; ++t) {
        // ---- wait for this slice's producers to publish epoch >= t ----
        if (t > 0) {
            unsigned int tt = (unsigned int)t;
            while (1) {
                ull f = ld_acq64(flagp);
                if ((unsigned int)f >= tt && (unsigned int)(f >> 32) >= tt) break;
            }
        }

        // ---- matvec partial over this warp's 64-k slice ----
        const float4* xb = (const float4*)(g_xbuf[t & 1][grp] + k0);
        ull acc[4] = {0ull, 0ull, 0ull, 0ull};
        #pragma unroll
        for (int i = 0; i < 16; ++i) {
            float4 x = ld_cg_f4(xb + i);   // uniform across warp -> broadcast
            fma2(acc[i & 3], pack2(x.x, x.y), A2[2*i]);
            fma2(acc[i & 3], pack2(x.z, x.w), A2[2*i+1]);
        }
        float2 f0 = unpack2(acc[0]), f1 = unpack2(acc[1]);
        float2 f2 = unpack2(acc[2]), f3 = unpack2(acc[3]);
        red[w*32 + l] = (f0.x + f0.y) + (f1.x + f1.y)
                      + (f2.x + f2.y) + (f3.x + f3.y);
        __syncthreads();

        // ---- writer warp: combine, tanh, publish next blended chunk ----
        if (tid < 32) {
            float s0 = 0.f, s1 = 0.f, s2 = 0.f, s3 = 0.f;
            #pragma unroll
            for (int ww = 0; ww < 16; ww += 4) {
                s0 += red[(ww+0)*32 + tid];
                s1 += red[(ww+1)*32 + tid];
                s2 += red[(ww+2)*32 + tid];
                s3 += red[(ww+3)*32 + tid];
            }
            float st = tanhf((s0 + s1) + (s2 + s3) + dval);
            g_states[((size_t)t*B + grp)*D + col] = st;
            if (t+1 < S) {
                g_xbuf[(t+1) & 1][grp][col] = gval * st;
                __syncwarp();
                if (tid == 0)
                    st_rel32(&g_flags[grp][cid], (unsigned int)(t + 1));
                dval = __ldcg(&g_c[((size_t)(t+1)*B + grp)*D + col]);
                gval = (t+2 < S) ? __ldcg(&g_gate[((size_t)(t+2)*B + grp)*D + col]) : 0.f;
            }
        }
        __syncthreads();   // protect red[] reuse next step
    }
}

// ---------------------------------------------------------------------------
// Launch
// ---------------------------------------------------------------------------
extern "C" void kernel_launch(void* const* d_in, const int* in_sizes, int n_in,
                              void* d_out, int out_size)
{
    const float* q   = (const float*)d_in[0];
    const float* k   = (const float*)d_in[1];
    const float* v   = (const float*)d_in[2];
    const float* Wi  = (const float*)d_in[3];
    const float* bi  = (const float*)d_in[4];
    const float* Wg  = (const float*)d_in[5];
    const float* bg  = (const float*)d_in[6];
    const float* A   = (const float*)d_in[7];
    const float* Bm  = (const float*)d_in[8];
    const float* Wo  = (const float*)d_in[9];
    const float* bo  = (const float*)d_in[10];
    const float* dec = (const float*)d_in[11];
    float* out = (float*)d_out;

    float *ret_p, *inp_p, *gpre_p, *c_p, *u_p, *states_p;
    cudaGetSymbolAddress((void**)&ret_p,    g_ret);
    cudaGetSymbolAddress((void**)&inp_p,    g_inp);
    cudaGetSymbolAddress((void**)&gpre_p,   g_gpre);
    cudaGetSymbolAddress((void**)&c_p,      g_c);
    cudaGetSymbolAddress((void**)&u_p,      g_u);
    cudaGetSymbolAddress((void**)&states_p, g_states);

    init_misc_kernel<<<16, 256>>>();

    dim3 sg(16, 4, 4);
    scan_kernel<<<sg, 256>>>(q, k, v, dec);

    dim3 gg(D/128, M_ROWS/128);   // (8, 64)
    sgemm_kernel<<<gg, 256>>>(ret_p, Wi, bi, nullptr, inp_p, 0);
    sgemm_kernel<<<gg, 256>>>(inp_p, Wg, bg, nullptr, gpre_p, 0);
    sgemm_kernel<<<gg, 256>>>(inp_p, Bm, nullptr, nullptr, c_p, 0);
    gate_kernel<<<M_ROWS*(D/256), 256>>>();
    sgemm_kernel<<<gg, 256>>>(u_p, A, nullptr, c_p, c_p, 0);
    seq_kernel<<<128, 512>>>(A);
    sgemm_kernel<<<gg, 256>>>(states_p, Wo, bo, nullptr, out, 1);
}

// round 11
// speedup vs baseline: 1.3611x; 1.3611x over previous
#include <cuda_runtime.h>
#include <math.h>

// Problem constants
#define S   2048
#define B   4
#define D   1024
#define M_ROWS (S*B)   // 8192 rows, time-major: row = t*B + b

typedef unsigned long long ull;

// ---------------------------------------------------------------------------
// Scratch buffers (device globals; no allocation allowed)
// ---------------------------------------------------------------------------
__device__ float g_ret   [(size_t)M_ROWS*D];
__device__ float g_inp   [(size_t)M_ROWS*D];
__device__ float g_gpre  [(size_t)M_ROWS*D];
__device__ float g_c     [(size_t)M_ROWS*D];   // c; later d = u@A^T + c
__device__ float g_gate  [(size_t)M_ROWS*D];
__device__ float g_u     [(size_t)M_ROWS*D];
__device__ float g_states[(size_t)M_ROWS*D];
__device__ float        g_xbuf[2][B][D];       // blended exchange, 2-deep
__device__ unsigned int g_flags[4][32];        // per-group per-producer epoch

__global__ void init_misc_kernel() {
    int i = blockIdx.x*blockDim.x + threadIdx.x;
    if (i < 4*32) ((unsigned int*)g_flags)[i] = 0u;
    if (i < B*D)  ((float*)g_xbuf)[i] = 0.f;   // buf0 = zeros (epoch 0)
}

// ---------------------------------------------------------------------------
// f32x2 + memory-order helpers
// ---------------------------------------------------------------------------
__device__ __forceinline__ ull pack2(float x, float y) {
    ull r; asm("mov.b64 %0, {%1, %2};" : "=l"(r) : "f"(x), "f"(y)); return r;
}
__device__ __forceinline__ void fma2(ull& d, ull a, ull b) {
    asm("fma.rn.f32x2 %0, %1, %2, %0;" : "+l"(d) : "l"(a), "l"(b));
}
__device__ __forceinline__ float2 unpack2(ull a) {
    float2 r; asm("mov.b64 {%0, %1}, %2;" : "=f"(r.x), "=f"(r.y) : "l"(a)); return r;
}
__device__ __forceinline__ unsigned int ld_acq32(const unsigned int* p) {
    unsigned int v;
    asm volatile("ld.acquire.gpu.u32 %0, [%1];" : "=r"(v) : "l"(p) : "memory");
    return v;
}
__device__ __forceinline__ void st_rel32(unsigned int* p, unsigned int v) {
    asm volatile("st.release.gpu.u32 [%0], %1;" :: "l"(p), "r"(v) : "memory");
}
__device__ __forceinline__ float4 ld_cg_f4(const float4* p) {
    float4 v;
    asm volatile("ld.global.cg.v4.f32 {%0,%1,%2,%3}, [%4];"
                 : "=f"(v.x), "=f"(v.y), "=f"(v.z), "=f"(v.w) : "l"(p) : "memory");
    return v;
}

// ---------------------------------------------------------------------------
// Phase 1: retention scan with decay halo (decay=0.9 -> 256-step halo exact
// to ~2e-12 relative).
// ---------------------------------------------------------------------------
__global__ void scan_kernel(const float* __restrict__ q,
                            const float* __restrict__ k,
                            const float* __restrict__ v,
                            const float* __restrict__ dec)
{
    int chunk = blockIdx.x;                 // 16 chunks of 128 steps
    int b     = blockIdx.y;
    int d     = blockIdx.z*256 + threadIdx.x;
    float decay = dec[d >> 6];
    int t0 = chunk*128;
    int start = t0 - 256; if (start < 0) start = 0;
    float r = 0.f;
    const float* kb = k + ((size_t)b*S)*D + d;
    const float* vb = v + ((size_t)b*S)*D + d;
    const float* qb = q + ((size_t)b*S)*D + d;
    for (int tt = start; tt < t0 + 128; ++tt) {
        size_t off = (size_t)tt*D;
        r = decay*r + kb[off]*vb[off];
        if (tt >= t0) g_ret[((size_t)tt*B + b)*D + d] = qb[off]*r;
    }
}

// ---------------------------------------------------------------------------
// fp32 SGEMM (round-6 version, measured 450us): 128x128 tile, BK=8, 256 thr,
// 8x8/thread, double-buffered smem, f32x2 FMA.
// ---------------------------------------------------------------------------
__global__ __launch_bounds__(256, 2)
void sgemm_kernel(const float* __restrict__ X, const float* __restrict__ W,
                  const float* __restrict__ bias, const float* Cin,
                  float* Cout, int permute)
{
    __shared__ float As[2][8][128];
    __shared__ float Bs[2][8][128];

    int tid = threadIdx.x;
    int m0 = blockIdx.y*128, n0 = blockIdx.x*128;
    int lrow = tid >> 1;
    int lk4  = (tid & 1)*4;
    const float4* Xg = (const float4*)(X + (size_t)(m0+lrow)*D + lk4);
    const float4* Wg = (const float4*)(W + (size_t)(n0+lrow)*D + lk4);
    int ty = tid >> 4, tx = tid & 15;

    ull acc[8][4];   // 8 rows x 4 col-pairs (f32x2 over adjacent n)
    #pragma unroll
    for (int i = 0; i < 8; ++i)
        #pragma unroll
        for (int j = 0; j < 4; ++j) acc[i][j] = 0ull;

    // prologue: fill buffer 0
    float4 ra = Xg[0], rb = Wg[0];
    As[0][lk4+0][lrow] = ra.x; As[0][lk4+1][lrow] = ra.y;
    As[0][lk4+2][lrow] = ra.z; As[0][lk4+3][lrow] = ra.w;
    Bs[0][lk4+0][lrow] = rb.x; Bs[0][lk4+1][lrow] = rb.y;
    Bs[0][lk4+2][lrow] = rb.z; Bs[0][lk4+3][lrow] = rb.w;
    __syncthreads();

    int cur = 0;
    #pragma unroll 1
    for (int kt = 0; kt < 128; ++kt) {
        float4 ra2, rb2;
        if (kt < 127) { ra2 = Xg[(kt+1)*2]; rb2 = Wg[(kt+1)*2]; }

        #pragma unroll
        for (int kk = 0; kk < 8; ++kk) {
            float4 a0 = *(const float4*)&As[cur][kk][ty*8];
            float4 a1 = *(const float4*)&As[cur][kk][ty*8+4];
            ulonglong2 b0 = *(const ulonglong2*)&Bs[cur][kk][tx*8];
            ulonglong2 b1 = *(const ulonglong2*)&Bs[cur][kk][tx*8+4];
            ull bp[4] = { b0.x, b0.y, b1.x, b1.y };
            ull ad[8];
            ad[0] = pack2(a0.x, a0.x); ad[1] = pack2(a0.y, a0.y);
            ad[2] = pack2(a0.z, a0.z); ad[3] = pack2(a0.w, a0.w);
            ad[4] = pack2(a1.x, a1.x); ad[5] = pack2(a1.y, a1.y);
            ad[6] = pack2(a1.z, a1.z); ad[7] = pack2(a1.w, a1.w);
            #pragma unroll
            for (int i = 0; i < 8; ++i)
                #pragma unroll
                for (int j = 0; j < 4; ++j)
                    fma2(acc[i][j], bp[j], ad[i]);
        }

        if (kt < 127) {
            int nb = cur ^ 1;
            As[nb][lk4+0][lrow] = ra2.x; As[nb][lk4+1][lrow] = ra2.y;
            As[nb][lk4+2][lrow] = ra2.z; As[nb][lk4+3][lrow] = ra2.w;
            Bs[nb][lk4+0][lrow] = rb2.x; Bs[nb][lk4+1][lrow] = rb2.y;
            Bs[nb][lk4+2][lrow] = rb2.z; Bs[nb][lk4+3][lrow] = rb2.w;
            __syncthreads();
            cur = nb;
        }
    }

    #pragma unroll
    for (int i = 0; i < 8; ++i) {
        int m = m0 + ty*8 + i;
        size_t obase;
        if (!permute) obase = (size_t)m*D;
        else { int t = m >> 2; int bb = m & 3; obase = ((size_t)bb*S + t)*D; }
        #pragma unroll
        for (int j = 0; j < 4; ++j) {
            float2 v = unpack2(acc[i][j]);
            int n = n0 + tx*8 + j*2;
            float v0 = v.x, v1 = v.y;
            if (bias) { v0 += bias[n]; v1 += bias[n+1]; }
            if (Cin)  { v0 += Cin[(size_t)m*D + n]; v1 += Cin[(size_t)m*D + n+1]; }
            Cout[obase + n]   = v0;
            Cout[obase + n+1] = v1;
        }
    }
}

// ---------------------------------------------------------------------------
// gate = sigmoid(gpre); u = (1-gate)*inp
// ---------------------------------------------------------------------------
__global__ void gate_kernel()
{
    size_t i = (size_t)blockIdx.x*blockDim.x + threadIdx.x;
    if (i < (size_t)M_ROWS*D) {
        float gp = g_gpre[i];
        float gt = 1.f/(1.f + expf(-gp));
        g_gate[i] = gt;
        g_u[i]    = (1.f - gt)*g_inp[i];
    }
}

// ---------------------------------------------------------------------------
// Sequential phase: state_t = tanh((g_t (*) state_{t-1}) @ A^T + d_t)
// 4 independent batch groups x 32 CTAs x 512 threads.
// Per-producer epoch flags (no atomic serialization) + CENTRALIZED polling:
// only warp 0 polls, lane l reads flag[grp][l] (one coalesced 128B acquire
// load per poll), __all_sync vote, __syncthreads releases the CTA.
// 2-deep xbuf + "all flags >= t before computing step t" => overwrite-safe.
// ---------------------------------------------------------------------------
__global__ __launch_bounds__(512, 1)
void seq_kernel(const float* __restrict__ A)
{
    __shared__ float red[16*32];

    int tid = threadIdx.x;
    int w   = tid >> 5, l = tid & 31;
    int grp = blockIdx.x & 3;          // batch
    int cid = blockIdx.x >> 2;         // 0..31 within group
    int col = cid*32 + l;
    int k0  = w*64;

    // Register-resident A slice: A[col, k0 .. k0+63] as 32 f32x2 pairs
    ull A2[32];
    {
        const ulonglong2* ap = (const ulonglong2*)(A + (size_t)col*D + k0);
        #pragma unroll
        for (int i = 0; i < 16; ++i) {
            ulonglong2 u = ap[i];
            A2[2*i] = u.x; A2[2*i+1] = u.y;
        }
    }

    unsigned int* myflag   = &g_flags[grp][cid];
    const unsigned int* pf = &g_flags[grp][l];     // warp-0 poll target

    // warp-0 lane prefetch: d row for step 0, gate row for step 1
    float dval = 0.f, gval = 0.f;
    if (w == 0) {
        dval = __ldg(&g_c   [(size_t)grp*D + col]);
        gval = __ldg(&g_gate[((size_t)1*B + grp)*D + col]);
    }

    for (int t = 0; t < S; ++t) {
        // ---- matvec partial over this warp's 64-k slice (xbuf ready) ----
        const float4* xb = (const float4*)(g_xbuf[t & 1][grp] + k0);
        ull acc[4] = {0ull, 0ull, 0ull, 0ull};
        #pragma unroll
        for (int i = 0; i < 16; ++i) {
            float4 x = ld_cg_f4(xb + i);   // uniform across warp -> broadcast
            fma2(acc[i & 3], pack2(x.x, x.y), A2[2*i]);
            fma2(acc[i & 3], pack2(x.z, x.w), A2[2*i+1]);
        }
        float2 f0 = unpack2(acc[0]), f1 = unpack2(acc[1]);
        float2 f2 = unpack2(acc[2]), f3 = unpack2(acc[3]);
        red[w*32 + l] = (f0.x + f0.y) + (f1.x + f1.y)
                      + (f2.x + f2.y) + (f3.x + f3.y);
        __syncthreads();

        // ---- warp 0: combine, tanh, publish, then poll for next step ----
        if (w == 0) {
            float s0 = 0.f, s1 = 0.f, s2 = 0.f, s3 = 0.f;
            #pragma unroll
            for (int ww = 0; ww < 16; ww += 4) {
                s0 += red[(ww+0)*32 + l];
                s1 += red[(ww+1)*32 + l];
                s2 += red[(ww+2)*32 + l];
                s3 += red[(ww+3)*32 + l];
            }
            float st = tanhf((s0 + s1) + (s2 + s3) + dval);
            g_states[((size_t)t*B + grp)*D + col] = st;
            if (t+1 < S) {
                g_xbuf[(t+1) & 1][grp][col] = gval * st;
                __syncwarp();
                if (l == 0)
                    st_rel32(myflag, (unsigned int)(t + 1));
                // prefetch next d/gate while others' flags propagate
                dval = __ldcg(&g_c[((size_t)(t+1)*B + grp)*D + col]);
                gval = (t+2 < S) ? __ldcg(&g_gate[((size_t)(t+2)*B + grp)*D + col]) : 0.f;
                // centralized poll: one coalesced acquire load per iteration
                unsigned int need = (unsigned int)(t + 1);
                while (!__all_sync(0xffffffffu, ld_acq32(pf) >= need)) { }
            }
        }
        __syncthreads();   // releases CTA for step t+1; also guards red[]
    }
}

// ---------------------------------------------------------------------------
// Launch
// ---------------------------------------------------------------------------
extern "C" void kernel_launch(void* const* d_in, const int* in_sizes, int n_in,
                              void* d_out, int out_size)
{
    const float* q   = (const float*)d_in[0];
    const float* k   = (const float*)d_in[1];
    const float* v   = (const float*)d_in[2];
    const float* Wi  = (const float*)d_in[3];
    const float* bi  = (const float*)d_in[4];
    const float* Wg  = (const float*)d_in[5];
    const float* bg  = (const float*)d_in[6];
    const float* A   = (const float*)d_in[7];
    const float* Bm  = (const float*)d_in[8];
    const float* Wo  = (const float*)d_in[9];
    const float* bo  = (const float*)d_in[10];
    const float* dec = (const float*)d_in[11];
    float* out = (float*)d_out;

    float *ret_p, *inp_p, *gpre_p, *c_p, *u_p, *states_p;
    cudaGetSymbolAddress((void**)&ret_p,    g_ret);
    cudaGetSymbolAddress((void**)&inp_p,    g_inp);
    cudaGetSymbolAddress((void**)&gpre_p,   g_gpre);
    cudaGetSymbolAddress((void**)&c_p,      g_c);
    cudaGetSymbolAddress((void**)&u_p,      g_u);
    cudaGetSymbolAddress((void**)&states_p, g_states);

    init_misc_kernel<<<16, 256>>>();

    dim3 sg(16, 4, 4);
    scan_kernel<<<sg, 256>>>(q, k, v, dec);

    dim3 gg(D/128, M_ROWS/128);   // (8, 64)
    sgemm_kernel<<<gg, 256>>>(ret_p, Wi, bi, nullptr, inp_p, 0);
    sgemm_kernel<<<gg, 256>>>(inp_p, Wg, bg, nullptr, gpre_p, 0);
    sgemm_kernel<<<gg, 256>>>(inp_p, Bm, nullptr, nullptr, c_p, 0);
    gate_kernel<<<M_ROWS*(D/256), 256>>>();
    sgemm_kernel<<<gg, 256>>>(u_p, A, nullptr, c_p, c_p, 0);
    seq_kernel<<<128, 512>>>(A);
    sgemm_kernel<<<gg, 256>>>(states_p, Wo, bo, nullptr, out, 1);
}